// round 4
// baseline (speedup 1.0000x reference)
#include <cuda_runtime.h>
#include <math.h>
#include <stdint.h>

#define Bn 4
#define Ln 128
#define Cn 6
#define EMBD 400
#define BL 512
#define KC1P 528           // padded hop-1 K (524 -> 528)
#define KFP 1048           // padded hop-2 K (1042 -> 1048)
#define KFULL 1042

// ---------------- scratch layout (floats) ----------------
#define O_EMB   0
#define O_PRE   (O_EMB + 204800)           // 2*512*1024
#define O_CTX   (O_PRE + 1048576)          // 512*512
#define O_Q     (O_CTX + 262144)
#define O_K     (O_Q + 262144)
#define O_CTX2  (O_K + 262144)
#define O_F     (O_CTX2 + 262144)          // 512*6
#define O_G     (O_F + 3072)
#define O_LM    (O_G + 3072)
#define O_F2    (O_LM + 3072)
#define O_G2    (O_F2 + 3072)
#define O_U     (O_G2 + 3072)              // 512*1024
#define O_V     (O_U + 524288)
#define O_U2    (O_V + 524288)
#define O_V2    (O_U2 + 524288)
#define O_ABU   (O_V2 + 524288)            // 512*528
#define O_ABV   (O_ABU + 270336)
#define O_WUC   (O_ABV + 270336)           // 1024*528
#define O_WVC   (O_WUC + 540672)
#define O_WPAD  (O_WVC + 540672)           // 1024*1048
#define O_UBAR  (O_WPAD + 1073152)         // 512*1048
#define O_VBAR  (O_UBAR + 536576)
#define SCRATCH_TOTAL (O_VBAR + 536576)

__device__ float d_scratch[SCRATCH_TOTAL];

// ---------------- embedding gather ----------------
__global__ void embed_kernel(const int* __restrict__ toks, const float* __restrict__ mask,
                             const float* __restrict__ gen, const float* __restrict__ dom,
                             float* __restrict__ emb) {
    int row = blockIdx.x;
    int tok = toks[row];
    float m = mask[row];
    for (int j = threadIdx.x; j < EMBD; j += blockDim.x) {
        float v = (j < 300) ? gen[tok * 300 + j] : dom[tok * 100 + (j - 300)];
        emb[row * EMBD + j] = v * m;
    }
}

// ---------------- z-batched SGEMM: C[M,N] = A[M,K] @ W[N,K]^T + bx + by ----------------
// BM=BN=64, BK=8, 4x4 microtile, double-buffered smem, float4 everywhere.
// Requires K % 8 == 0, lda/ldw/ldc % 4 == 0, M,N multiples of 64.
__global__ __launch_bounds__(256, 2)
void sgemm2(const float* __restrict__ A0, const float* __restrict__ A1, int lda,
            const float* __restrict__ W0, const float* __restrict__ W1, int ldw,
            const float* __restrict__ bx0, const float* __restrict__ by0,
            const float* __restrict__ bx1, const float* __restrict__ by1,
            float* __restrict__ C0, float* __restrict__ C1, int ldc, int K)
{
    __shared__ float sm[2][2][8][68];   // [buf][side][kk][m-or-n]
    const int z = blockIdx.z;
    const float* A = z ? A1 : A0;
    const float* W = z ? W1 : W0;
    const float* bx = z ? bx1 : bx0;
    const float* by = z ? by1 : by0;
    float* C = z ? C1 : C0;
    const int m0 = blockIdx.y * 64, n0 = blockIdx.x * 64;
    const int tid = threadIdx.x;
    const int side = tid >> 7;          // 0 -> A tile, 1 -> W tile
    const int lrow = (tid & 127) >> 1;  // 0..63
    const int lq = tid & 1;             // which half of the 8-wide k slab
    const float* g = side ? (W + (size_t)(n0 + lrow) * ldw + lq * 4)
                          : (A + (size_t)(m0 + lrow) * lda + lq * 4);
    const int tr = tid >> 4, tc = tid & 15;

    float acc[4][4];
#pragma unroll
    for (int i = 0; i < 4; i++)
#pragma unroll
        for (int j = 0; j < 4; j++) acc[i][j] = 0.f;

    const int T = K >> 3;
    float4 v = *(const float4*)g;
    {
        float* sb = &sm[0][side][0][0];
        sb[(lq * 4 + 0) * 68 + lrow] = v.x;
        sb[(lq * 4 + 1) * 68 + lrow] = v.y;
        sb[(lq * 4 + 2) * 68 + lrow] = v.z;
        sb[(lq * 4 + 3) * 68 + lrow] = v.w;
    }
    __syncthreads();

    for (int t = 0; t < T; t++) {
        if (t + 1 < T) v = *(const float4*)(g + (size_t)(t + 1) * 8);
        const float* As = &sm[t & 1][0][0][0];
        const float* Bs = &sm[t & 1][1][0][0];
#pragma unroll
        for (int kk = 0; kk < 8; kk++) {
            float4 ra = *(const float4*)(As + kk * 68 + tr * 4);
            float4 rb = *(const float4*)(Bs + kk * 68 + tc * 4);
            acc[0][0] = fmaf(ra.x, rb.x, acc[0][0]);
            acc[0][1] = fmaf(ra.x, rb.y, acc[0][1]);
            acc[0][2] = fmaf(ra.x, rb.z, acc[0][2]);
            acc[0][3] = fmaf(ra.x, rb.w, acc[0][3]);
            acc[1][0] = fmaf(ra.y, rb.x, acc[1][0]);
            acc[1][1] = fmaf(ra.y, rb.y, acc[1][1]);
            acc[1][2] = fmaf(ra.y, rb.z, acc[1][2]);
            acc[1][3] = fmaf(ra.y, rb.w, acc[1][3]);
            acc[2][0] = fmaf(ra.z, rb.x, acc[2][0]);
            acc[2][1] = fmaf(ra.z, rb.y, acc[2][1]);
            acc[2][2] = fmaf(ra.z, rb.z, acc[2][2]);
            acc[2][3] = fmaf(ra.z, rb.w, acc[2][3]);
            acc[3][0] = fmaf(ra.w, rb.x, acc[3][0]);
            acc[3][1] = fmaf(ra.w, rb.y, acc[3][1]);
            acc[3][2] = fmaf(ra.w, rb.z, acc[3][2]);
            acc[3][3] = fmaf(ra.w, rb.w, acc[3][3]);
        }
        if (t + 1 < T) {
            float* sb = &sm[(t + 1) & 1][side][0][0];
            sb[(lq * 4 + 0) * 68 + lrow] = v.x;
            sb[(lq * 4 + 1) * 68 + lrow] = v.y;
            sb[(lq * 4 + 2) * 68 + lrow] = v.z;
            sb[(lq * 4 + 3) * 68 + lrow] = v.w;
        }
        __syncthreads();
    }

    float bb[4];
#pragma unroll
    for (int j = 0; j < 4; j++) {
        int n = n0 + tc * 4 + j;
        float b = 0.f;
        if (bx) b += bx[n];
        if (by) b += by[n];
        bb[j] = b;
    }
#pragma unroll
    for (int i = 0; i < 4; i++) {
        float4 o;
        o.x = acc[i][0] + bb[0];
        o.y = acc[i][1] + bb[1];
        o.z = acc[i][2] + bb[2];
        o.w = acc[i][3] + bb[3];
        *(float4*)(C + (size_t)(m0 + tr * 4 + i) * ldc + n0 + tc * 4) = o;
    }
}

// ---------------- BiLSTM via 8-CTA clusters (one cluster per dir x batch) ----------------
__global__ __launch_bounds__(256, 1) __cluster_dims__(8, 1, 1)
void lstm_cluster(const float* __restrict__ whh_f, const float* __restrict__ whh_b,
                  const float* __restrict__ pre,   // [2][512][1024]
                  float* __restrict__ ctx)         // [512][512]
{
    __shared__ float hb[2][264];     // h double buffer; second half at +132 (bank pad)
    const int tid = threadIdx.x;
    unsigned rank;
    asm("mov.u32 %0, %%cluster_ctarank;" : "=r"(rank));
    const int cid = blockIdx.x >> 3;
    const int dir = cid >> 2;
    const int batch = cid & 3;
    const int ct = (int)rank * 256 + tid;   // 0..2047 cluster thread id
    const int half = ct & 1;
    const int p = ct >> 1;                  // 0..1023 gate-row pair
    const int gate = p & 3;                 // i,f,g,o
    const int d = p >> 2;                   // hidden dim 0..255
    const int lane = tid & 31;
    const int gbase = lane & ~7;
    const bool prod = (ct & 7) == 0;        // owner of dim d: computes c,h
    const int dslot = (d < 128) ? d : d + 4;

    const float* whh = dir ? whh_b : whh_f;
    float4 w[32];
    {
        const float4* wp = (const float4*)(whh + ((size_t)(gate * 256 + d)) * 256 + half * 128);
#pragma unroll
        for (int i = 0; i < 32; i++) w[i] = wp[i];
    }
    for (int j = tid; j < 264; j += 256) hb[0][j] = 0.f;

    const float* preB = pre + ((size_t)dir * 512 + batch * 128) * 1024 + gate * 256 + d;
    float* ctxB = ctx + ((size_t)batch * 128) * 512 + dir * 256 + d;

    uint32_t la0 = (uint32_t)__cvta_generic_to_shared(&hb[0][dslot]);
    uint32_t la1 = (uint32_t)__cvta_generic_to_shared(&hb[1][dslot]);

    asm volatile("barrier.cluster.arrive.aligned;" ::: "memory");
    float preCur = preB[(size_t)(dir ? 127 : 0) * 1024];
    float cc = 0.f;

    for (int s = 0; s < 128; s++) {
        asm volatile("barrier.cluster.wait.aligned;" ::: "memory");
        const float4* hp = (const float4*)(&hb[s & 1][half ? 132 : 0]);
        float acc = 0.f;
#pragma unroll
        for (int i = 0; i < 32; i++) {
            float4 hv = hp[i];
            acc = fmaf(w[i].x, hv.x, acc);
            acc = fmaf(w[i].y, hv.y, acc);
            acc = fmaf(w[i].z, hv.z, acc);
            acc = fmaf(w[i].w, hv.w, acc);
        }
        acc += __shfl_xor_sync(0xffffffffu, acc, 1);
        float gv = acc + preCur;
        float gi = __shfl_sync(0xffffffffu, gv, gbase);
        float gf = __shfl_sync(0xffffffffu, gv, gbase + 2);
        float gg = __shfl_sync(0xffffffffu, gv, gbase + 4);
        float go = __shfl_sync(0xffffffffu, gv, gbase + 6);
        int time = dir ? (127 - s) : s;
        if (prod) {
            float ii = 1.f / (1.f + expf(-gi));
            float ff = 1.f / (1.f + expf(-gf));
            float oo = 1.f / (1.f + expf(-go));
            float gt = tanhf(gg);
            cc = ff * cc + ii * gt;
            float hv = oo * tanhf(cc);
            uint32_t la = ((s + 1) & 1) ? la1 : la0;
#pragma unroll
            for (int r = 0; r < 8; r++) {
                uint32_t ra;
                asm("mapa.shared::cluster.u32 %0, %1, %2;" : "=r"(ra) : "r"(la), "r"(r));
                asm volatile("st.shared::cluster.f32 [%0], %1;" :: "r"(ra), "f"(hv));
            }
            ctxB[(size_t)time * 512] = hv;
        }
        asm volatile("barrier.cluster.arrive.aligned;" ::: "memory");
        if (s < 127) {
            int tn = dir ? (126 - s) : (s + 1);
            preCur = preB[(size_t)tn * 1024];
        }
    }
    asm volatile("barrier.cluster.wait.aligned;" ::: "memory");
}

// ---------------- self-attention + residual ----------------
__global__ __launch_bounds__(256)
void attn_kernel(const float* __restrict__ q, const float* __restrict__ k,
                 const float* __restrict__ ctx, float* __restrict__ ctx2) {
    int row = blockIdx.x;
    int b = row >> 7;
    int tid = threadIdx.x;
    __shared__ float qsh[512];
    __shared__ float sc[128];
    __shared__ float red[128];
    for (int j = tid; j < 512; j += 256) qsh[j] = q[(size_t)row * 512 + j];
    __syncthreads();
    {
        int m = tid >> 1, half = tid & 1;
        const float* kr = k + ((size_t)(b * 128 + m)) * 512 + half * 256;
        const float* qh = qsh + half * 256;
        float s = 0.f;
#pragma unroll 8
        for (int j = 0; j < 256; j++) s = fmaf(qh[j], kr[j], s);
        s += __shfl_xor_sync(0xffffffffu, s, 1);
        if (!half) sc[m] = s;
    }
    __syncthreads();
    if (tid < 128) red[tid] = sc[tid];
    __syncthreads();
    for (int s = 64; s > 0; s >>= 1) {
        if (tid < s) red[tid] = fmaxf(red[tid], red[tid + s]);
        __syncthreads();
    }
    float mx = red[0];
    __syncthreads();
    if (tid < 128) { float e = expf(sc[tid] - mx); sc[tid] = e; red[tid] = e; }
    __syncthreads();
    for (int s = 64; s > 0; s >>= 1) {
        if (tid < s) red[tid] += red[tid + s];
        __syncthreads();
    }
    float inv = 1.f / red[0];
    __syncthreads();
    int c0 = tid * 2;
    float o0 = 0.f, o1 = 0.f;
    for (int m = 0; m < 128; m++) {
        float a = sc[m] * inv;
        float2 cv = *reinterpret_cast<const float2*>(ctx + ((size_t)(b * 128 + m)) * 512 + c0);
        o0 = fmaf(a, cv.x, o0);
        o1 = fmaf(a, cv.y, o1);
    }
    float2 base = *reinterpret_cast<const float2*>(ctx + (size_t)row * 512 + c0);
    float2 o; o.x = o0 + base.x; o.y = o1 + base.y;
    *reinterpret_cast<float2*>(ctx2 + (size_t)row * 512 + c0) = o;
}

// ---------------- z-paired thin matmul -> 6 classes per row ----------------
__global__ __launch_bounds__(256)
void smallmm2(const float* __restrict__ A0, const float* __restrict__ A1, int lda, int K,
              const float* __restrict__ W, int ldw, int off0, int off1,
              const float* __restrict__ bias, float* __restrict__ C0, float* __restrict__ C1) {
    int z = blockIdx.z;
    const float* A = (z ? A1 : A0) + (size_t)blockIdx.x * lda;
    int off = z ? off1 : off0;
    float* C = (z ? C1 : C0) + (size_t)blockIdx.x * Cn;
    int tid = threadIdx.x;
    float acc[Cn] = {0, 0, 0, 0, 0, 0};
    for (int k4 = tid; k4 * 4 < K; k4 += 256) {
        float4 a = *(const float4*)(A + k4 * 4);
#pragma unroll
        for (int c = 0; c < Cn; c++) {
            float4 wv = *(const float4*)(W + (size_t)c * ldw + off + k4 * 4);
            acc[c] += a.x * wv.x + a.y * wv.y + a.z * wv.z + a.w * wv.w;
        }
    }
    __shared__ float red[Cn][256];
#pragma unroll
    for (int c = 0; c < Cn; c++) red[c][tid] = acc[c];
    __syncthreads();
    for (int s = 128; s > 0; s >>= 1) {
        if (tid < s)
#pragma unroll
            for (int c = 0; c < Cn; c++) red[c][tid] += red[c][tid + s];
        __syncthreads();
    }
    if (tid < Cn) C[tid] = red[tid][0] + ((z == 0 && bias) ? bias[tid] : 0.f);
}

// ---------------- lm via prefix/suffix masked maxes ----------------
__global__ void lm_kernel(const float* __restrict__ F, const float* __restrict__ G,
                          float* __restrict__ LM) {
    int t = threadIdx.x;
    if (t >= Bn * Cn) return;
    int b = t / Cn, c = t % Cn;
    const float* Fb = F + (size_t)(b * Ln) * Cn + c;
    const float* Gb = G + (size_t)(b * Ln) * Cn + c;
    float* Lb = LM + (size_t)(b * Ln) * Cn + c;
    float pf = -3.0e38f;
    for (int l = 0; l < Ln; l++) {
        pf = fmaxf(pf, Fb[l * Cn]);
        float v = Gb[l * Cn] + pf;
        if (l < Ln - 1) v = fmaxf(v, 0.f);
        Lb[l * Cn] = v;
    }
    float sg = -3.0e38f;
    for (int l = Ln - 1; l >= 0; l--) {
        sg = fmaxf(sg, Gb[l * Cn]);
        float v = Fb[l * Cn] + sg;
        if (l > 0) v = fmaxf(v, 0.f);
        Lb[l * Cn] = fmaxf(Lb[l * Cn], v);
    }
}

// ---------------- feat_w gathers (compact hop-1 slices + padded full copy) ----------------
__global__ void gather_w(const float* __restrict__ feat_w,
                         float* __restrict__ wUc, float* __restrict__ wVc) {
    int idx = blockIdx.x * blockDim.x + threadIdx.x;
    if (idx >= 1024 * KC1P) return;
    int n = idx / KC1P, j = idx % KC1P;
    float u = 0.f, v = 0.f;
    if (j < 524) {
        int srcU = (j < 512) ? j : ((j < 518) ? 1024 + (j - 512) : 1036 + (j - 518));
        int srcV = (j < 512) ? 512 + j : ((j < 518) ? 1030 + (j - 512) : 1036 + (j - 518));
        u = feat_w[(size_t)n * KFULL + srcU];
        v = feat_w[(size_t)n * KFULL + srcV];
    }
    wUc[idx] = u;
    wVc[idx] = v;
}

__global__ void gather_wpad(const float* __restrict__ feat_w, float* __restrict__ wp) {
    int idx = blockIdx.x * blockDim.x + threadIdx.x;
    if (idx >= 1024 * KFP) return;
    int n = idx / KFP, j = idx % KFP;
    wp[idx] = (j < KFULL) ? feat_w[(size_t)n * KFULL + j] : 0.f;
}

__global__ void build_ab1(const float* __restrict__ ctx2, const float* __restrict__ LM,
                          const float* __restrict__ F, const float* __restrict__ G,
                          float* __restrict__ AbU, float* __restrict__ AbV) {
    int row = blockIdx.x;
    for (int j = threadIdx.x; j < KC1P; j += blockDim.x) {
        float u = 0.f, v = 0.f;
        if (j < 512) { u = v = ctx2[(size_t)row * 512 + j]; }
        else if (j < 518) { u = v = LM[(size_t)row * Cn + (j - 512)]; }
        else if (j < 524) { u = F[(size_t)row * Cn + (j - 518)]; v = G[(size_t)row * Cn + (j - 518)]; }
        AbU[(size_t)row * KC1P + j] = u;
        AbV[(size_t)row * KC1P + j] = v;
    }
}

__global__ void build_bar(const float* __restrict__ U, const float* __restrict__ V,
                          const float* __restrict__ LM,
                          const float* __restrict__ F, const float* __restrict__ G,
                          float* __restrict__ Ub, float* __restrict__ Vb) {
    int row = blockIdx.x;
    for (int j = threadIdx.x; j < KFP; j += blockDim.x) {
        float u = 0.f, v = 0.f;
        if (j < 1024) { u = U[(size_t)row * 1024 + j]; v = V[(size_t)row * 1024 + j]; }
        else if (j < 1030) { u = LM[(size_t)row * Cn + (j - 1024)]; v = 0.f; }
        else if (j < 1036) { u = 0.f; v = LM[(size_t)row * Cn + (j - 1030)]; }
        else if (j < 1042) { u = F[(size_t)row * Cn + (j - 1036)]; v = G[(size_t)row * Cn + (j - 1036)]; }
        Ub[(size_t)row * KFP + j] = u;
        Vb[(size_t)row * KFP + j] = v;
    }
}

__global__ void final_kernel(const float* __restrict__ F, const float* __restrict__ G,
                             float* __restrict__ out) {
    int idx = blockIdx.x * blockDim.x + threadIdx.x;
    if (idx >= Bn * Ln * Ln * Cn) return;
    int c = idx % Cn;
    int j = (idx / Cn) % Ln;
    int i = (idx / (Cn * Ln)) % Ln;
    int b = idx / (Cn * Ln * Ln);
    out[idx] = F[((size_t)(b * Ln + i)) * Cn + c] + G[((size_t)(b * Ln + j)) * Cn + c];
}

extern "C" void kernel_launch(void* const* d_in, const int* in_sizes, int n_in,
                              void* d_out, int out_size) {
    (void)in_sizes; (void)n_in; (void)out_size;
    const int*   toks   = (const int*)  d_in[0];
    const float* mask   = (const float*)d_in[2];
    const float* gen    = (const float*)d_in[3];
    const float* dom    = (const float*)d_in[4];
    const float* wih_f  = (const float*)d_in[5];
    const float* whh_f  = (const float*)d_in[6];
    const float* bih_f  = (const float*)d_in[7];
    const float* bhh_f  = (const float*)d_in[8];
    const float* wih_b  = (const float*)d_in[9];
    const float* whh_b  = (const float*)d_in[10];
    const float* bih_b  = (const float*)d_in[11];
    const float* bhh_b  = (const float*)d_in[12];
    const float* wq     = (const float*)d_in[13];
    const float* bq     = (const float*)d_in[14];
    const float* wk     = (const float*)d_in[15];
    const float* bk     = (const float*)d_in[16];
    const float* feat_w = (const float*)d_in[17];
    const float* feat_b = (const float*)d_in[18];
    const float* cls_w  = (const float*)d_in[19];
    const float* cls_b  = (const float*)d_in[20];
    float* out = (float*)d_out;

    float* S = nullptr;
    cudaGetSymbolAddress((void**)&S, d_scratch);
    float* emb  = S + O_EMB;
    float* pre  = S + O_PRE;
    float* ctx  = S + O_CTX;
    float* qb   = S + O_Q;
    float* kb   = S + O_K;
    float* ctx2 = S + O_CTX2;
    float* F    = S + O_F;
    float* G    = S + O_G;
    float* LM   = S + O_LM;
    float* F2   = S + O_F2;
    float* G2   = S + O_G2;
    float* U    = S + O_U;
    float* V    = S + O_V;
    float* U2   = S + O_U2;
    float* V2   = S + O_V2;
    float* AbU  = S + O_ABU;
    float* AbV  = S + O_ABV;
    float* wUc  = S + O_WUC;
    float* wVc  = S + O_WVC;
    float* Wpad = S + O_WPAD;
    float* Ubar = S + O_UBAR;
    float* Vbar = S + O_VBAR;

    embed_kernel<<<BL, 128>>>(toks, mask, gen, dom, emb);
    gather_w<<<(1024 * KC1P + 255) / 256, 256>>>(feat_w, wUc, wVc);
    gather_wpad<<<(1024 * KFP + 255) / 256, 256>>>(feat_w, Wpad);

    // pre-activations (both dirs in one launch): emb @ wih^T + bih + bhh
    sgemm2<<<dim3(16, 8, 2), 256>>>(emb, emb, EMBD, wih_f, wih_b, EMBD,
                                    bih_f, bhh_f, bih_b, bhh_b,
                                    pre, pre + (size_t)BL * 1024, 1024, EMBD);

    lstm_cluster<<<64, 256>>>(whh_f, whh_b, pre, ctx);

    // q/k projections in one launch
    sgemm2<<<dim3(8, 8, 2), 256>>>(ctx, ctx, 512, wq, wk, 512,
                                   bq, nullptr, bk, nullptr,
                                   qb, kb, 512, 512);
    attn_kernel<<<BL, 256>>>(qb, kb, ctx, ctx2);

    // F0 = ctx2 @ cls_w[:, :512]^T + cls_b ; G0 = ctx2 @ cls_w[:, 512:]^T
    smallmm2<<<dim3(BL, 1, 2), 256>>>(ctx2, ctx2, 512, 512, cls_w, 1024, 0, 512, cls_b, F, G);

    // ---- hop 1 (compact K=528) ----
    lm_kernel<<<1, 32>>>(F, G, LM);
    build_ab1<<<BL, 256>>>(ctx2, LM, F, G, AbU, AbV);
    sgemm2<<<dim3(16, 8, 2), 256>>>(AbU, AbV, KC1P, wUc, wVc, KC1P,
                                    feat_b, nullptr, nullptr, nullptr,
                                    U, V, 1024, KC1P);
    smallmm2<<<dim3(BL, 1, 2), 256>>>(U, V, 1024, 1024, cls_w, 1024, 0, 0, cls_b, F2, G2);

    // ---- hop 2 (padded K=1048) ----
    lm_kernel<<<1, 32>>>(F2, G2, LM);
    build_bar<<<BL, 256>>>(U, V, LM, F2, G2, Ubar, Vbar);
    sgemm2<<<dim3(16, 8, 2), 256>>>(Ubar, Vbar, KFP, Wpad, Wpad, KFP,
                                    feat_b, nullptr, nullptr, nullptr,
                                    U2, V2, 1024, KFP);
    smallmm2<<<dim3(BL, 1, 2), 256>>>(U2, V2, 1024, 1024, cls_w, 1024, 0, 0, cls_b, F, G);

    final_kernel<<<1536, 256>>>(F, G, out);
}

// round 6
// speedup vs baseline: 1.1327x; 1.1327x over previous
#include <cuda_runtime.h>
#include <cuda_bf16.h>
#include <math.h>
#include <stdint.h>

#define Bn 4
#define Ln 128
#define Cn 6
#define BL 512
#define KC1P 528
#define KFP 1056
#define KFULL 1042

#define O_EMB   0
#define O_PRE   (O_EMB + 204800)
#define O_CTX   (O_PRE + 1048576)
#define O_Q     (O_CTX + 262144)
#define O_K     (O_Q + 262144)
#define O_CTX2  (O_K + 262144)
#define O_F     (O_CTX2 + 262144)
#define O_G     (O_F + 3072)
#define O_LM    (O_G + 3072)
#define O_F2    (O_LM + 3072)
#define O_G2    (O_F2 + 3072)
#define O_U     (O_G2 + 3072)
#define O_V     (O_U + 524288)
#define O_U2    (O_V + 524288)
#define O_V2    (O_U2 + 524288)
#define O_ABU   (O_V2 + 524288)
#define O_ABV   (O_ABU + 270336)
#define O_WUC   (O_ABV + 270336)
#define O_WVC   (O_WUC + 540672)
#define O_WPAD  (O_WVC + 540672)
#define O_UBAR  (O_WPAD + 1081344)
#define O_VBAR  (O_UBAR + 540672)
#define SCRATCH_TOTAL (O_VBAR + 540672)
__device__ float d_scratch[SCRATCH_TOTAL];

static __device__ __forceinline__ uint32_t smem_u32(const void* p) {
    uint32_t a;
    asm("{ .reg .u64 t; cvta.to.shared.u64 t, %1; cvt.u32.u64 %0, t; }" : "=r"(a) : "l"(p));
    return a;
}
static __device__ __forceinline__ void cvt2(float x, float y, uint32_t& h, uint32_t& l) {
    __nv_bfloat16 hx = __float2bfloat16_rn(x), hy = __float2bfloat16_rn(y);
    __nv_bfloat16 lx = __float2bfloat16_rn(x - __bfloat162float(hx));
    __nv_bfloat16 ly = __float2bfloat16_rn(y - __bfloat162float(hy));
    h = (uint32_t)__bfloat16_as_ushort(hx) | ((uint32_t)__bfloat16_as_ushort(hy) << 16);
    l = (uint32_t)__bfloat16_as_ushort(lx) | ((uint32_t)__bfloat16_as_ushort(ly) << 16);
}
#define LDSM4(R, a) asm volatile("ldmatrix.sync.aligned.m8n8.x4.shared.b16 {%0,%1,%2,%3}, [%4];" \
    : "=r"((R)[0]), "=r"((R)[1]), "=r"((R)[2]), "=r"((R)[3]) : "r"(a))
#define MMA(c, a, b0, b1) asm volatile( \
    "mma.sync.aligned.m16n8k16.row.col.f32.bf16.bf16.f32 {%0,%1,%2,%3},{%4,%5,%6,%7},{%8,%9},{%0,%1,%2,%3};" \
    : "+f"((c)[0]), "+f"((c)[1]), "+f"((c)[2]), "+f"((c)[3]) \
    : "r"((a)[0]), "r"((a)[1]), "r"((a)[2]), "r"((a)[3]), "r"(b0), "r"(b1))

// byte offsets inside one buffer (pitch 48B, 16 bf16 data + 16B pad per row)
#define AHI 0
#define ALO 6144
#define WHI 12288
#define WLO 15360
#define BUFSZ 18432

// C[M,N] = A[M,K] @ W[N,K]^T + bx + by.  Tiles 128x64, BK=16, bf16 3-term split, K%16==0.
__global__ __launch_bounds__(256, 1)
void mmgemm(const float* __restrict__ A0, const float* __restrict__ A1, int lda,
            const float* __restrict__ W0, const float* __restrict__ W1, int ldw,
            const float* __restrict__ bx0, const float* __restrict__ by0,
            const float* __restrict__ bx1, const float* __restrict__ by1,
            float* __restrict__ C0, float* __restrict__ C1, int ldc, int K)
{
    __shared__ __align__(16) char sm[2 * BUFSZ];
    const int z = blockIdx.z;
    const float* A = z ? A1 : A0;
    const float* W = z ? W1 : W0;
    const float* bx = z ? bx1 : bx0;
    const float* by = z ? by1 : by0;
    float* C = z ? C1 : C0;
    const int m0 = blockIdx.y * 128, n0 = blockIdx.x * 64;
    const int tid = threadIdx.x, w = tid >> 5, L = tid & 31;
    const int wm = (w & 3) * 32, wn = (w >> 2) * 32;
    const uint32_t sb = smem_u32(sm);

    // ldmatrix per-lane offsets (within buffer)
    uint32_t offA[2], offB[2];
    {
        int r = (L & 7) + ((L >> 3) & 1) * 8, ko = ((L >> 4) & 1) * 16;
        offA[0] = (uint32_t)((wm + r) * 48 + ko);
        offA[1] = (uint32_t)((wm + 16 + r) * 48 + ko);
        int br = (L & 7) + ((L >> 4) & 1) * 8, bko = ((L >> 3) & 1) * 16;
        offB[0] = (uint32_t)(WHI + (wn + br) * 48 + bko);
        offB[1] = (uint32_t)(WHI + (wn + 16 + br) * 48 + bko);
    }
    float c[2][4][4];
#pragma unroll
    for (int i = 0; i < 2; i++)
#pragma unroll
        for (int j = 0; j < 4; j++)
#pragma unroll
            for (int q = 0; q < 4; q++) c[i][j][q] = 0.f;

    const int T = K >> 4;
    const int ar0 = tid >> 2, aq = tid & 3;     // A writer: rows tid>>2 & +64, 4 floats each
    const int wr = tid >> 2, wq = tid & 3;      // W writer
    float4 ga0, ga1, gw;

    // preload chunk 0
    ga0 = *(const float4*)(A + (size_t)(m0 + ar0) * lda + aq * 4);
    ga1 = *(const float4*)(A + (size_t)(m0 + 64 + ar0) * lda + aq * 4);
    gw  = *(const float4*)(W + (size_t)(n0 + wr) * ldw + wq * 4);
    {
        char* bp = sm;
        uint32_t h0, l0, h1, l1;
        cvt2(ga0.x, ga0.y, h0, l0); cvt2(ga0.z, ga0.w, h1, l1);
        *(uint2*)(bp + AHI + ar0 * 48 + aq * 8) = make_uint2(h0, h1);
        *(uint2*)(bp + ALO + ar0 * 48 + aq * 8) = make_uint2(l0, l1);
        cvt2(ga1.x, ga1.y, h0, l0); cvt2(ga1.z, ga1.w, h1, l1);
        *(uint2*)(bp + AHI + (64 + ar0) * 48 + aq * 8) = make_uint2(h0, h1);
        *(uint2*)(bp + ALO + (64 + ar0) * 48 + aq * 8) = make_uint2(l0, l1);
        cvt2(gw.x, gw.y, h0, l0); cvt2(gw.z, gw.w, h1, l1);
        *(uint2*)(bp + WHI + wr * 48 + wq * 8) = make_uint2(h0, h1);
        *(uint2*)(bp + WLO + wr * 48 + wq * 8) = make_uint2(l0, l1);
    }
    __syncthreads();

    for (int t = 0; t < T; t++) {
        if (t + 1 < T) {
            int k0 = (t + 1) << 4;
            ga0 = *(const float4*)(A + (size_t)(m0 + ar0) * lda + k0 + aq * 4);
            ga1 = *(const float4*)(A + (size_t)(m0 + 64 + ar0) * lda + k0 + aq * 4);
            gw  = *(const float4*)(W + (size_t)(n0 + wr) * ldw + k0 + wq * 4);
        }
        {
            uint32_t base = sb + (uint32_t)((t & 1) * BUFSZ);
            uint32_t ah[2][4], al[2][4], bh[2][4], bl[2][4];
#pragma unroll
            for (int mf = 0; mf < 2; mf++) {
                LDSM4(ah[mf], base + offA[mf]);
                LDSM4(al[mf], base + ALO + offA[mf]);
            }
#pragma unroll
            for (int g = 0; g < 2; g++) {
                LDSM4(bh[g], base + offB[g]);
                LDSM4(bl[g], base + (WLO - WHI) + offB[g]);
            }
#pragma unroll
            for (int mf = 0; mf < 2; mf++)
#pragma unroll
                for (int nf = 0; nf < 4; nf++) {
                    int g = nf >> 1, o = (nf & 1) * 2;
                    MMA(c[mf][nf], ah[mf], bh[g][o], bh[g][o + 1]);
                    MMA(c[mf][nf], ah[mf], bl[g][o], bl[g][o + 1]);
                    MMA(c[mf][nf], al[mf], bh[g][o], bh[g][o + 1]);
                }
        }
        if (t + 1 < T) {
            char* bp = sm + ((t + 1) & 1) * BUFSZ;
            uint32_t h0, l0, h1, l1;
            cvt2(ga0.x, ga0.y, h0, l0); cvt2(ga0.z, ga0.w, h1, l1);
            *(uint2*)(bp + AHI + ar0 * 48 + aq * 8) = make_uint2(h0, h1);
            *(uint2*)(bp + ALO + ar0 * 48 + aq * 8) = make_uint2(l0, l1);
            cvt2(ga1.x, ga1.y, h0, l0); cvt2(ga1.z, ga1.w, h1, l1);
            *(uint2*)(bp + AHI + (64 + ar0) * 48 + aq * 8) = make_uint2(h0, h1);
            *(uint2*)(bp + ALO + (64 + ar0) * 48 + aq * 8) = make_uint2(l0, l1);
            cvt2(gw.x, gw.y, h0, l0); cvt2(gw.z, gw.w, h1, l1);
            *(uint2*)(bp + WHI + wr * 48 + wq * 8) = make_uint2(h0, h1);
            *(uint2*)(bp + WLO + wr * 48 + wq * 8) = make_uint2(l0, l1);
        }
        __syncthreads();
    }

    // writeback
    const int g = L >> 2, qc = (L & 3) * 2;
#pragma unroll
    for (int nf = 0; nf < 4; nf++) {
        int col = n0 + wn + nf * 8 + qc;
        float b0 = 0.f, b1 = 0.f;
        if (bx) { b0 += bx[col]; b1 += bx[col + 1]; }
        if (by) { b0 += by[col]; b1 += by[col + 1]; }
#pragma unroll
        for (int mf = 0; mf < 2; mf++) {
            int row = m0 + wm + mf * 16 + g;
            *(float2*)(C + (size_t)row * ldc + col) = make_float2(c[mf][nf][0] + b0, c[mf][nf][1] + b1);
            *(float2*)(C + (size_t)(row + 8) * ldc + col) = make_float2(c[mf][nf][2] + b0, c[mf][nf][3] + b1);
        }
    }
}

__global__ void embed_kernel(const int* __restrict__ toks, const float* __restrict__ mask,
                             const float* __restrict__ gen, const float* __restrict__ dom,
                             float* __restrict__ emb) {
    int row = blockIdx.x, tok = toks[row];
    float m = mask[row];
    for (int j = threadIdx.x; j < 400; j += blockDim.x) {
        float v = (j < 300) ? gen[tok * 300 + j] : dom[tok * 100 + (j - 300)];
        emb[(size_t)row * 400 + j] = v * m;
    }
}

__global__ void gather_w(const float* __restrict__ fw, float* __restrict__ wUc, float* __restrict__ wVc) {
    int idx = blockIdx.x * blockDim.x + threadIdx.x;
    if (idx >= 1024 * KC1P) return;
    int n = idx / KC1P, j = idx % KC1P;
    float u = 0.f, v = 0.f;
    if (j < 524) {
        int sU = (j < 512) ? j : ((j < 518) ? 1024 + (j - 512) : 1036 + (j - 518));
        int sV = (j < 512) ? 512 + j : ((j < 518) ? 1030 + (j - 512) : 1036 + (j - 518));
        u = fw[(size_t)n * KFULL + sU];
        v = fw[(size_t)n * KFULL + sV];
    }
    wUc[idx] = u; wVc[idx] = v;
}

__global__ void gather_wpad(const float* __restrict__ fw, float* __restrict__ wp) {
    int idx = blockIdx.x * blockDim.x + threadIdx.x;
    if (idx >= 1024 * KFP) return;
    int n = idx / KFP, j = idx % KFP;
    wp[idx] = (j < KFULL) ? fw[(size_t)n * KFULL + j] : 0.f;
}

__global__ __launch_bounds__(256, 1) __cluster_dims__(8, 1, 1)
void lstm_cluster(const float* __restrict__ whh_f, const float* __restrict__ whh_b,
                  const float* __restrict__ pre, float* __restrict__ ctx) {
    __shared__ float hb[2][264];
    const int tid = threadIdx.x;
    unsigned rank;
    asm("mov.u32 %0, %%cluster_ctarank;" : "=r"(rank));
    const int cid = blockIdx.x >> 3, dir = cid >> 2, batch = cid & 3;
    const int ct = (int)rank * 256 + tid;
    const int half = ct & 1, p = ct >> 1, gate = p & 3, d = p >> 2;
    const int gbase = (tid & 31) & ~7;
    const bool prod = (ct & 7) == 0;
    const int dslot = (d < 128) ? d : d + 4;
    const float* whh = dir ? whh_b : whh_f;
    float4 w[32];
    const float4* wp = (const float4*)(whh + ((size_t)(gate * 256 + d)) * 256 + half * 128);
#pragma unroll
    for (int i = 0; i < 32; i++) w[i] = wp[i];
    for (int j = tid; j < 264; j += 256) hb[0][j] = 0.f;
    const float* preB = pre + ((size_t)dir * 512 + batch * 128) * 1024 + gate * 256 + d;
    float* ctxB = ctx + ((size_t)batch * 128) * 512 + dir * 256 + d;
    uint32_t la0 = (uint32_t)__cvta_generic_to_shared(&hb[0][dslot]);
    uint32_t la1 = (uint32_t)__cvta_generic_to_shared(&hb[1][dslot]);
    asm volatile("barrier.cluster.arrive.aligned;" ::: "memory");
    float preCur = preB[(size_t)(dir ? 127 : 0) * 1024];
    float cc = 0.f;
    for (int s = 0; s < 128; s++) {
        asm volatile("barrier.cluster.wait.aligned;" ::: "memory");
        const float4* hp = (const float4*)(&hb[s & 1][half ? 132 : 0]);
        float acc = 0.f;
#pragma unroll
        for (int i = 0; i < 32; i++) {
            float4 hv = hp[i];
            acc = fmaf(w[i].x, hv.x, acc);
            acc = fmaf(w[i].y, hv.y, acc);
            acc = fmaf(w[i].z, hv.z, acc);
            acc = fmaf(w[i].w, hv.w, acc);
        }
        acc += __shfl_xor_sync(0xffffffffu, acc, 1);
        float gv = acc + preCur;
        float gi = __shfl_sync(0xffffffffu, gv, gbase);
        float gf = __shfl_sync(0xffffffffu, gv, gbase + 2);
        float gg = __shfl_sync(0xffffffffu, gv, gbase + 4);
        float go = __shfl_sync(0xffffffffu, gv, gbase + 6);
        int time = dir ? (127 - s) : s;
        if (prod) {
            float ii = 1.f / (1.f + expf(-gi));
            float ff = 1.f / (1.f + expf(-gf));
            float oo = 1.f / (1.f + expf(-go));
            cc = ff * cc + ii * tanhf(gg);
            float hv = oo * tanhf(cc);
            uint32_t la = ((s + 1) & 1) ? la1 : la0;
#pragma unroll
            for (int r = 0; r < 8; r++) {
                uint32_t ra;
                asm("mapa.shared::cluster.u32 %0, %1, %2;" : "=r"(ra) : "r"(la), "r"(r));
                asm volatile("st.shared::cluster.f32 [%0], %1;" :: "r"(ra), "f"(hv));
            }
            ctxB[(size_t)time * 512] = hv;
        }
        asm volatile("barrier.cluster.arrive.aligned;" ::: "memory");
        if (s < 127) preCur = preB[(size_t)(dir ? (126 - s) : (s + 1)) * 1024];
    }
    asm volatile("barrier.cluster.wait.aligned;" ::: "memory");
}

__global__ __launch_bounds__(256)
void attn_kernel(const float* __restrict__ q, const float* __restrict__ k,
                 const float* __restrict__ ctx, float* __restrict__ ctx2) {
    int row = blockIdx.x, b = row >> 7, tid = threadIdx.x;
    __shared__ float qsh[512], sc[128], red[128];
    for (int j = tid; j < 512; j += 256) qsh[j] = q[(size_t)row * 512 + j];
    __syncthreads();
    {
        int m = tid >> 1, half = tid & 1;
        const float* kr = k + ((size_t)(b * 128 + m)) * 512 + half * 256;
        const float* qh = qsh + half * 256;
        float s = 0.f;
#pragma unroll 8
        for (int j = 0; j < 256; j++) s = fmaf(qh[j], kr[j], s);
        s += __shfl_xor_sync(0xffffffffu, s, 1);
        if (!half) sc[m] = s;
    }
    __syncthreads();
    if (tid < 128) red[tid] = sc[tid];
    __syncthreads();
    for (int s = 64; s > 0; s >>= 1) {
        if (tid < s) red[tid] = fmaxf(red[tid], red[tid + s]);
        __syncthreads();
    }
    float mx = red[0];
    __syncthreads();
    if (tid < 128) { float e = expf(sc[tid] - mx); sc[tid] = e; red[tid] = e; }
    __syncthreads();
    for (int s = 64; s > 0; s >>= 1) {
        if (tid < s) red[tid] += red[tid + s];
        __syncthreads();
    }
    float inv = 1.f / red[0];
    __syncthreads();
    int c0 = tid * 2;
    float o0 = 0.f, o1 = 0.f;
    for (int m = 0; m < 128; m++) {
        float a = sc[m] * inv;
        float2 cv = *(const float2*)(ctx + ((size_t)(b * 128 + m)) * 512 + c0);
        o0 = fmaf(a, cv.x, o0);
        o1 = fmaf(a, cv.y, o1);
    }
    float2 bs = *(const float2*)(ctx + (size_t)row * 512 + c0);
    *(float2*)(ctx2 + (size_t)row * 512 + c0) = make_float2(o0 + bs.x, o1 + bs.y);
}

__global__ __launch_bounds__(256)
void smallmm2(const float* __restrict__ A0, const float* __restrict__ A1, int lda, int K,
              const float* __restrict__ W, int ldw, int off0, int off1,
              const float* __restrict__ bias, float* __restrict__ C0, float* __restrict__ C1) {
    int z = blockIdx.z;
    const float* A = (z ? A1 : A0) + (size_t)blockIdx.x * lda;
    int off = z ? off1 : off0;
    float* C = (z ? C1 : C0) + (size_t)blockIdx.x * Cn;
    int tid = threadIdx.x;
    float acc[Cn] = {0, 0, 0, 0, 0, 0};
    for (int k4 = tid; k4 * 4 < K; k4 += 256) {
        float4 a = *(const float4*)(A + k4 * 4);
#pragma unroll
        for (int c = 0; c < Cn; c++) {
            float4 wv = *(const float4*)(W + (size_t)c * ldw + off + k4 * 4);
            acc[c] += a.x * wv.x + a.y * wv.y + a.z * wv.z + a.w * wv.w;
        }
    }
    __shared__ float red[Cn][256];
#pragma unroll
    for (int c = 0; c < Cn; c++) red[c][tid] = acc[c];
    __syncthreads();
    for (int s = 128; s > 0; s >>= 1) {
        if (tid < s)
#pragma unroll
            for (int c = 0; c < Cn; c++) red[c][tid] += red[c][tid + s];
        __syncthreads();
    }
    if (tid < Cn) C[tid] = red[tid][0] + ((z == 0 && bias) ? bias[tid] : 0.f);
}

__global__ void lm_kernel(const float* __restrict__ F, const float* __restrict__ G, float* __restrict__ LM) {
    int t = threadIdx.x;
    if (t >= Bn * Cn) return;
    int b = t / Cn, c = t % Cn;
    const float* Fb = F + (size_t)(b * Ln) * Cn + c;
    const float* Gb = G + (size_t)(b * Ln) * Cn + c;
    float* Lb = LM + (size_t)(b * Ln) * Cn + c;
    float pf = -3.0e38f;
    for (int l = 0; l < Ln; l++) {
        pf = fmaxf(pf, Fb[l * Cn]);
        float v = Gb[l * Cn] + pf;
        if (l < Ln - 1) v = fmaxf(v, 0.f);
        Lb[l * Cn] = v;
    }
    float sg = -3.0e38f;
    for (int l = Ln - 1; l >= 0; l--) {
        sg = fmaxf(sg, Gb[l * Cn]);
        float v = Fb[l * Cn] + sg;
        if (l > 0) v = fmaxf(v, 0.f);
        Lb[l * Cn] = fmaxf(Lb[l * Cn], v);
    }
}

__global__ void build_ab1(const float* __restrict__ ctx2, const float* __restrict__ LM,
                          const float* __restrict__ F, const float* __restrict__ G,
                          float* __restrict__ AbU, float* __restrict__ AbV) {
    int row = blockIdx.x;
    for (int j = threadIdx.x; j < KC1P; j += blockDim.x) {
        float u = 0.f, v = 0.f;
        if (j < 512) { u = v = ctx2[(size_t)row * 512 + j]; }
        else if (j < 518) { u = v = LM[(size_t)row * Cn + (j - 512)]; }
        else if (j < 524) { u = F[(size_t)row * Cn + (j - 518)]; v = G[(size_t)row * Cn + (j - 518)]; }
        AbU[(size_t)row * KC1P + j] = u;
        AbV[(size_t)row * KC1P + j] = v;
    }
}

__global__ void build_bar(const float* __restrict__ U, const float* __restrict__ V,
                          const float* __restrict__ LM, const float* __restrict__ F,
                          const float* __restrict__ G, float* __restrict__ Ub, float* __restrict__ Vb) {
    int row = blockIdx.x;
    for (int j = threadIdx.x; j < KFP; j += blockDim.x) {
        float u = 0.f, v = 0.f;
        if (j < 1024) { u = U[(size_t)row * 1024 + j]; v = V[(size_t)row * 1024 + j]; }
        else if (j < 1030) { u = LM[(size_t)row * Cn + (j - 1024)]; }
        else if (j < 1036) { v = LM[(size_t)row * Cn + (j - 1030)]; }
        else if (j < 1042) { u = F[(size_t)row * Cn + (j - 1036)]; v = G[(size_t)row * Cn + (j - 1036)]; }
        Ub[(size_t)row * KFP + j] = u;
        Vb[(size_t)row * KFP + j] = v;
    }
}

__global__ void final_kernel(const float* __restrict__ F, const float* __restrict__ G, float* __restrict__ out) {
    int idx = blockIdx.x * blockDim.x + threadIdx.x;
    if (idx >= Bn * Ln * Ln * Cn) return;
    int c = idx % Cn, j = (idx / Cn) % Ln, i = (idx / (Cn * Ln)) % Ln, b = idx / (Cn * Ln * Ln);
    out[idx] = F[((size_t)(b * Ln + i)) * Cn + c] + G[((size_t)(b * Ln + j)) * Cn + c];
}

extern "C" void kernel_launch(void* const* d_in, const int* in_sizes, int n_in,
                              void* d_out, int out_size) {
    (void)in_sizes; (void)n_in; (void)out_size;
    const int* toks = (const int*)d_in[0];
    const float* mask = (const float*)d_in[2];
    const float* gen = (const float*)d_in[3];
    const float* dom = (const float*)d_in[4];
    const float* wih_f = (const float*)d_in[5];
    const float* whh_f = (const float*)d_in[6];
    const float* bih_f = (const float*)d_in[7];
    const float* bhh_f = (const float*)d_in[8];
    const float* wih_b = (const float*)d_in[9];
    const float* whh_b = (const float*)d_in[10];
    const float* bih_b = (const float*)d_in[11];
    const float* bhh_b = (const float*)d_in[12];
    const float* wq = (const float*)d_in[13];
    const float* bq = (const float*)d_in[14];
    const float* wk = (const float*)d_in[15];
    const float* bk = (const float*)d_in[16];
    const float* feat_w = (const float*)d_in[17];
    const float* feat_b = (const float*)d_in[18];
    const float* cls_w = (const float*)d_in[19];
    const float* cls_b = (const float*)d_in[20];
    float* out = (float*)d_out;

    float* S = nullptr;
    cudaGetSymbolAddress((void**)&S, d_scratch);
    float* emb = S + O_EMB;    float* pre = S + O_PRE;   float* ctx = S + O_CTX;
    float* qb = S + O_Q;       float* kb = S + O_K;      float* ctx2 = S + O_CTX2;
    float* F = S + O_F;        float* G = S + O_G;       float* LM = S + O_LM;
    float* F2 = S + O_F2;      float* G2 = S + O_G2;     float* U = S + O_U;
    float* V = S + O_V;        float* U2 = S + O_U2;     float* V2 = S + O_V2;
    float* AbU = S + O_ABU;    float* AbV = S + O_ABV;   float* wUc = S + O_WUC;
    float* wVc = S + O_WVC;    float* Wp = S + O_WPAD;
    float* Ub = S + O_UBAR;    float* Vb = S + O_VBAR;

    embed_kernel<<<BL, 128>>>(toks, mask, gen, dom, emb);
    gather_w<<<(1024 * KC1P + 255) / 256, 256>>>(feat_w, wUc, wVc);
    gather_wpad<<<(1024 * KFP + 255) / 256, 256>>>(feat_w, Wp);

    mmgemm<<<dim3(16, 4, 2), 256>>>(emb, emb, 400, wih_f, wih_b, 400,
                                    bih_f, bhh_f, bih_b, bhh_b,
                                    pre, pre + (size_t)BL * 1024, 1024, 400);
    lstm_cluster<<<64, 256>>>(whh_f, whh_b, pre, ctx);

    mmgemm<<<dim3(8, 4, 2), 256>>>(ctx, ctx, 512, wq, wk, 512,
                                   bq, nullptr, bk, nullptr, qb, kb, 512, 512);
    attn_kernel<<<BL, 256>>>(qb, kb, ctx, ctx2);
    smallmm2<<<dim3(BL, 1, 2), 256>>>(ctx2, ctx2, 512, 512, cls_w, 1024, 0, 512, cls_b, F, G);

    lm_kernel<<<1, 32>>>(F, G, LM);
    build_ab1<<<BL, 256>>>(ctx2, LM, F, G, AbU, AbV);
    mmgemm<<<dim3(16, 4, 2), 256>>>(AbU, AbV, KC1P, wUc, wVc, KC1P,
                                    feat_b, nullptr, nullptr, nullptr, U, V, 1024, KC1P);
    smallmm2<<<dim3(BL, 1, 2), 256>>>(U, V, 1024, 1024, cls_w, 1024, 0, 0, cls_b, F2, G2);

    lm_kernel<<<1, 32>>>(F2, G2, LM);
    build_bar<<<BL, 256>>>(U, V, LM, F2, G2, Ub, Vb);
    mmgemm<<<dim3(16, 4, 2), 256>>>(Ub, Vb, KFP, Wp, Wp, KFP,
                                    feat_b, nullptr, nullptr, nullptr, U2, V2, 1024, KFP);
    smallmm2<<<dim3(BL, 1, 2), 256>>>(U2, V2, 1024, 1024, cls_w, 1024, 0, 0, cls_b, F, G);

    final_kernel<<<1536, 256>>>(F, G, out);
}